// round 1
// baseline (speedup 1.0000x reference)
#include <cuda_runtime.h>
#include <cuda_bf16.h>

#define B_   2
#define T_   2048
#define D_   768
#define H_   12
#define DH_  64
#define M_   (B_ * T_)   // 4096

// ---------------- scratch (static device globals; no allocation) ----------------
__device__ float g_Q [B_ * H_ * T_ * DH_];   // [B,H,T,Dh]
__device__ float g_K [B_ * H_ * T_ * DH_];
__device__ float g_V [B_ * H_ * T_ * DH_];
__device__ float g_VS[B_ * H_ * T_ * DH_];   // suffix sums of V
__device__ float g_AO[M_ * D_];              // attention out, [B,T, H*Dh]

// ---------------- GEMM: C[M,768] = A[M,768] @ W[768,768] + bias -----------------
// scatter=1: write into [B,H,T,Dh] buffer (QKV). scatter=0: plain row-major.
__global__ __launch_bounds__(256)
void gemm_kernel(const float* __restrict__ A, const float* __restrict__ W,
                 const float* __restrict__ bias, float* __restrict__ C, int scatter)
{
    __shared__ float As[64][36];   // [m][k], padded
    __shared__ float Ws[32][68];   // [k][n], padded

    const int tx = threadIdx.x, ty = threadIdx.y;
    const int tid = ty * 16 + tx;
    const int m0 = blockIdx.y * 64;
    const int n0 = blockIdx.x * 64;

    float acc[4][4];
#pragma unroll
    for (int i = 0; i < 4; i++)
#pragma unroll
        for (int j = 0; j < 4; j++) acc[i][j] = 0.f;

    for (int kk = 0; kk < D_; kk += 32) {
        // A tile: 64x32 floats = 512 float4, 2 per thread
#pragma unroll
        for (int r = 0; r < 2; r++) {
            int idx = tid + r * 256;           // 0..511
            int row = idx >> 3;                // 8 float4 per row
            int q4  = idx & 7;
            float4 v = *(const float4*)(A + (size_t)(m0 + row) * D_ + kk + q4 * 4);
            *(float4*)&As[row][q4 * 4] = v;
        }
        // W tile: 32x64 floats = 512 float4
#pragma unroll
        for (int r = 0; r < 2; r++) {
            int idx = tid + r * 256;
            int kr = idx >> 4;                 // 16 float4 per row
            int n4 = idx & 15;
            float4 v = *(const float4*)(W + (size_t)(kk + kr) * D_ + n0 + n4 * 4);
            *(float4*)&Ws[kr][n4 * 4] = v;
        }
        __syncthreads();

#pragma unroll
        for (int k = 0; k < 32; k++) {
            float a[4], b[4];
#pragma unroll
            for (int i = 0; i < 4; i++) a[i] = As[ty * 4 + i][k];
#pragma unroll
            for (int j = 0; j < 4; j++) b[j] = Ws[k][tx * 4 + j];
#pragma unroll
            for (int i = 0; i < 4; i++)
#pragma unroll
                for (int j = 0; j < 4; j++) acc[i][j] = fmaf(a[i], b[j], acc[i][j]);
        }
        __syncthreads();
    }

#pragma unroll
    for (int i = 0; i < 4; i++) {
        int m = m0 + ty * 4 + i;
#pragma unroll
        for (int j = 0; j < 4; j++) {
            int n = n0 + tx * 4 + j;
            float val = acc[i][j] + bias[n];
            if (scatter) {
                int b  = m / T_;
                int t  = m - b * T_;
                int h  = n >> 6;      // n / 64
                int dh = n & 63;
                C[((size_t)(b * H_ + h) * T_ + t) * DH_ + dh] = val;
            } else {
                C[(size_t)m * D_ + n] = val;
            }
        }
    }
}

// ---------------- V suffix sums per (b,h): VS[t] = sum_{j>t} V[j] ----------------
__global__ __launch_bounds__(256)
void vsuffix_kernel()
{
    const int bh = blockIdx.x;                 // 0..23
    const float* V = g_V  + (size_t)bh * T_ * DH_;
    float*       S = g_VS + (size_t)bh * T_ * DH_;
    const int d = threadIdx.x;                 // 0..63
    const int c = threadIdx.y;                 // 0..3 chunk
    __shared__ float ctot[4][64];

    const int t0 = c * 512;
    float sum = 0.f;
    for (int t = t0 + 511; t >= t0; t--) {
        S[(size_t)t * DH_ + d] = sum;
        sum += V[(size_t)t * DH_ + d];
    }
    ctot[c][d] = sum;
    __syncthreads();

    float off = 0.f;
    for (int cc = c + 1; cc < 4; cc++) off += ctot[cc][d];
    if (c != 3) {
        for (int t = t0; t < t0 + 512; t++)
            S[(size_t)t * DH_ + d] += off;
    }
}

// ---------------- fused causal attention (zero-fill semantics) -------------------
// grid (32 q-tiles, 24 bh), block (16,16). Dynamic smem.
#define QS(r,c) Qs[(r) * 65 + (c)]
#define KS(r,c) Ks[(r) * 65 + (c)]
#define VT(r,c) Vt[(r) * 65 + (c)]
#define PS(r,c) Ps[(r) * 68 + (c)]

__global__ __launch_bounds__(256)
void attn_kernel()
{
    extern __shared__ float sm[];
    float* Qs = sm;                 // 64 x 65
    float* Ks = sm + 4160;          // 64 x 65
    float* Vt = sm + 8320;          // 64 x 65
    float* Ps = sm + 12480;         // 64 x 68

    const int tx = threadIdx.x, ty = threadIdx.y;
    const int tid = ty * 16 + tx;
    const int bh = blockIdx.y;
    const int qt = blockIdx.x;
    const int q0 = qt * 64;

    const float* Q    = g_Q  + (size_t)bh * T_ * DH_;
    const float* K    = g_K  + (size_t)bh * T_ * DH_;
    const float* V    = g_V  + (size_t)bh * T_ * DH_;
    const float* Vsuf = g_VS + (size_t)bh * T_ * DH_;

    // load Q tile [64][64]
#pragma unroll
    for (int r = 0; r < 4; r++) {
        int idx = tid + r * 256;      // 0..1023
        int row = idx >> 4;
        int q4  = idx & 15;
        float4 v = *(const float4*)(Q + (size_t)(q0 + row) * DH_ + q4 * 4);
        QS(row, q4 * 4 + 0) = v.x; QS(row, q4 * 4 + 1) = v.y;
        QS(row, q4 * 4 + 2) = v.z; QS(row, q4 * 4 + 3) = v.w;
    }

    float o[4][4];
    float rsum[4];
#pragma unroll
    for (int i = 0; i < 4; i++) {
        rsum[i] = 0.f;
#pragma unroll
        for (int j = 0; j < 4; j++) o[i][j] = 0.f;
    }

    for (int kt = 0; kt <= qt; kt++) {
        __syncthreads();   // previous GEMM2 done reading Ks/Vt
        // load K,V tiles
#pragma unroll
        for (int r = 0; r < 4; r++) {
            int idx = tid + r * 256;
            int row = idx >> 4;
            int q4  = idx & 15;
            float4 vk = *(const float4*)(K + (size_t)(kt * 64 + row) * DH_ + q4 * 4);
            KS(row, q4 * 4 + 0) = vk.x; KS(row, q4 * 4 + 1) = vk.y;
            KS(row, q4 * 4 + 2) = vk.z; KS(row, q4 * 4 + 3) = vk.w;
            float4 vv = *(const float4*)(V + (size_t)(kt * 64 + row) * DH_ + q4 * 4);
            VT(row, q4 * 4 + 0) = vv.x; VT(row, q4 * 4 + 1) = vv.y;
            VT(row, q4 * 4 + 2) = vv.z; VT(row, q4 * 4 + 3) = vv.w;
        }
        __syncthreads();

        // S = Q . K^T  (inner dim = d)
        float s[4][4];
#pragma unroll
        for (int i = 0; i < 4; i++)
#pragma unroll
            for (int j = 0; j < 4; j++) s[i][j] = 0.f;

#pragma unroll 16
        for (int k = 0; k < 64; k++) {
            float a[4], b[4];
#pragma unroll
            for (int i = 0; i < 4; i++) a[i] = QS(ty * 4 + i, k);
#pragma unroll
            for (int j = 0; j < 4; j++) b[j] = KS(tx * 4 + j, k);
#pragma unroll
            for (int i = 0; i < 4; i++)
#pragma unroll
                for (int j = 0; j < 4; j++) s[i][j] = fmaf(a[i], b[j], s[i][j]);
        }

        // exp (no max-sub needed: |s/8| small), diagonal-tile mask, row sums, stage P
        const bool diag = (kt == qt);
#pragma unroll
        for (int i = 0; i < 4; i++) {
            int qi = q0 + ty * 4 + i;
#pragma unroll
            for (int j = 0; j < 4; j++) {
                int key = kt * 64 + tx * 4 + j;
                float p = (diag && key > qi) ? 0.f : __expf(s[i][j] * 0.125f);
                rsum[i] += p;
                PS(ty * 4 + i, tx * 4 + j) = p;
            }
        }
        __syncthreads();

        // O += P . V  (inner dim = key)
#pragma unroll 16
        for (int k = 0; k < 64; k++) {
            float a[4], b[4];
#pragma unroll
            for (int i = 0; i < 4; i++) a[i] = PS(ty * 4 + i, k);
#pragma unroll
            for (int j = 0; j < 4; j++) b[j] = VT(k, tx * 4 + j);
#pragma unroll
            for (int i = 0; i < 4; i++)
#pragma unroll
                for (int j = 0; j < 4; j++) o[i][j] = fmaf(a[i], b[j], o[i][j]);
        }
    }

    // reduce rsum across the 16 tx-lanes of each row group
#pragma unroll
    for (int i = 0; i < 4; i++) {
        float r = rsum[i];
        r += __shfl_xor_sync(0xffffffffu, r, 1);
        r += __shfl_xor_sync(0xffffffffu, r, 2);
        r += __shfl_xor_sync(0xffffffffu, r, 4);
        r += __shfl_xor_sync(0xffffffffu, r, 8);
        rsum[i] = r;
    }

    const int b = bh / H_;
    const int h = bh - b * H_;
#pragma unroll
    for (int i = 0; i < 4; i++) {
        int qi = q0 + ty * 4 + i;
        float denom = rsum[i] + (float)(T_ - 1 - qi);   // masked positions contribute exp(0)=1
        float inv = 1.f / denom;
#pragma unroll
        for (int j = 0; j < 4; j++) {
            int dh = tx * 4 + j;
            float num = o[i][j] + Vsuf[(size_t)qi * DH_ + dh];  // masked contribute 1*v_j
            g_AO[((size_t)(b * T_ + qi)) * D_ + h * DH_ + dh] = num * inv;
        }
    }
}

// ---------------- launch -----------------
extern "C" void kernel_launch(void* const* d_in, const int* in_sizes, int n_in,
                              void* d_out, int out_size)
{
    const float* X  = (const float*)d_in[0];
    const float* Wq = (const float*)d_in[1];
    const float* bq = (const float*)d_in[2];
    const float* Wk = (const float*)d_in[3];
    const float* bk = (const float*)d_in[4];
    const float* Wv = (const float*)d_in[5];
    const float* bv = (const float*)d_in[6];
    const float* Wo = (const float*)d_in[7];
    const float* bo = (const float*)d_in[8];
    float* out = (float*)d_out;

    const int ATTN_SMEM = (64 * 65 * 3 + 64 * 68) * 4;   // 67328 B
    cudaFuncSetAttribute(attn_kernel, cudaFuncAttributeMaxDynamicSharedMemorySize, ATTN_SMEM);

    float* Qp; cudaGetSymbolAddress((void**)&Qp, g_Q);
    float* Kp; cudaGetSymbolAddress((void**)&Kp, g_K);
    float* Vp; cudaGetSymbolAddress((void**)&Vp, g_V);
    float* AOp; cudaGetSymbolAddress((void**)&AOp, g_AO);

    dim3 blk(16, 16);
    dim3 ggrid(D_ / 64, M_ / 64);     // (12, 64)

    gemm_kernel<<<ggrid, blk>>>(X, Wq, bq, Qp, 1);
    gemm_kernel<<<ggrid, blk>>>(X, Wk, bk, Kp, 1);
    gemm_kernel<<<ggrid, blk>>>(X, Wv, bv, Vp, 1);
    vsuffix_kernel<<<B_ * H_, dim3(64, 4)>>>();
    attn_kernel<<<dim3(T_ / 64, B_ * H_), blk, ATTN_SMEM>>>();
    gemm_kernel<<<ggrid, blk>>>(AOp, Wo, bo, out, 0);
}

// round 2
// speedup vs baseline: 1.6414x; 1.6414x over previous
#include <cuda_runtime.h>
#include <cuda_bf16.h>
#include <cstdint>

#define B_   2
#define T_   2048
#define D_   768
#define H_   12
#define DH_  64
#define M_   (B_ * T_)   // 4096

// ---------------- scratch (static device globals; no allocation) ----------------
__device__ float g_Q [B_ * H_ * T_ * DH_];   // [B,H,T,Dh]
__device__ float g_K [B_ * H_ * T_ * DH_];
__device__ float g_V [B_ * H_ * T_ * DH_];
__device__ float g_VS[B_ * H_ * T_ * DH_];   // suffix sums of V
__device__ float g_AO[M_ * D_];              // attention out, [B,T, H*Dh]
__device__ float g_CT[24 * 32 * DH_];        // per-chunk V totals

// ---------------- tf32 helpers ----------------
__device__ __forceinline__ uint32_t f2tf32(float x) {
    uint32_t u;
    asm("cvt.rna.tf32.f32 %0, %1;" : "=r"(u) : "f"(x));
    return u;
}

#define MMA_TF32(c, a, b)                                                        \
    asm volatile(                                                                \
        "mma.sync.aligned.m16n8k8.row.col.f32.tf32.tf32.f32 "                    \
        "{%0,%1,%2,%3},{%4,%5,%6,%7},{%8,%9},{%0,%1,%2,%3};"                     \
        : "+f"((c)[0]), "+f"((c)[1]), "+f"((c)[2]), "+f"((c)[3])                 \
        : "r"((a)[0]), "r"((a)[1]), "r"((a)[2]), "r"((a)[3]),                    \
          "r"((b)[0]), "r"((b)[1]))

// ---------------- tensor-core GEMM: C[M,768] = A[M,768] @ W[768,768] + bias ----
// Block tile 128x64, k-chunk 32. 256 threads = 8 warps in 4(m) x 2(n); each warp
// computes a 32x32 tile via m16n8k8 tf32 mma (2 m-frags x 4 n-frags x 4 k-steps).
// scatter=1: write into [B,H,T,Dh] buffer (QKV). scatter=0: plain row-major.
__global__ __launch_bounds__(256)
void gemm_tc(const float* __restrict__ A, const float* __restrict__ W,
             const float* __restrict__ bias, float* __restrict__ C, int scatter)
{
    __shared__ float As[128][36];   // pad 36: A-frag LDS conflict-free (36%32=4)
    __shared__ float Ws[32][72];    // pad 72: B-frag LDS conflict-free (72%32=8)

    const int tid  = threadIdx.x;
    const int lane = tid & 31;
    const int wid  = tid >> 5;
    const int wm   = wid & 3;        // 0..3 -> 32-row slab
    const int wn   = wid >> 2;       // 0..1 -> 32-col slab
    const int m0   = blockIdx.y * 128;
    const int n0   = blockIdx.x * 64;

    float c[2][4][4];
#pragma unroll
    for (int mi = 0; mi < 2; mi++)
#pragma unroll
        for (int ni = 0; ni < 4; ni++)
#pragma unroll
            for (int r = 0; r < 4; r++) c[mi][ni][r] = 0.f;

    for (int kk = 0; kk < D_; kk += 32) {
        // A tile 128x32 = 1024 float4, 4 per thread
#pragma unroll
        for (int r = 0; r < 4; r++) {
            int idx = tid + r * 256;
            int row = idx >> 3;
            int c4  = idx & 7;
            float4 v = *(const float4*)(A + (size_t)(m0 + row) * D_ + kk + c4 * 4);
            *(float4*)&As[row][c4 * 4] = v;
        }
        // W tile 32x64 = 512 float4, 2 per thread
#pragma unroll
        for (int r = 0; r < 2; r++) {
            int idx = tid + r * 256;
            int kr  = idx >> 4;
            int c4  = idx & 15;
            float4 v = *(const float4*)(W + (size_t)(kk + kr) * D_ + n0 + c4 * 4);
            *(float4*)&Ws[kr][c4 * 4] = v;
        }
        __syncthreads();

#pragma unroll
        for (int ks = 0; ks < 4; ks++) {
            const int k0 = ks * 8;
            uint32_t a[2][4], b[4][2];
            const int ac = k0 + (lane & 3);
#pragma unroll
            for (int mi = 0; mi < 2; mi++) {
                int ar = wm * 32 + mi * 16 + (lane >> 2);
                a[mi][0] = f2tf32(As[ar][ac]);
                a[mi][1] = f2tf32(As[ar + 8][ac]);
                a[mi][2] = f2tf32(As[ar][ac + 4]);
                a[mi][3] = f2tf32(As[ar + 8][ac + 4]);
            }
#pragma unroll
            for (int ni = 0; ni < 4; ni++) {
                int col = wn * 32 + ni * 8 + (lane >> 2);
                b[ni][0] = f2tf32(Ws[k0 + (lane & 3)][col]);
                b[ni][1] = f2tf32(Ws[k0 + 4 + (lane & 3)][col]);
            }
#pragma unroll
            for (int mi = 0; mi < 2; mi++)
#pragma unroll
                for (int ni = 0; ni < 4; ni++)
                    MMA_TF32(c[mi][ni], a[mi], b[ni]);
        }
        __syncthreads();
    }

    // epilogue: c-frag (row=l/4 [+8], col=2*(l%4) [+1])
#pragma unroll
    for (int mi = 0; mi < 2; mi++) {
#pragma unroll
        for (int ni = 0; ni < 4; ni++) {
#pragma unroll
            for (int r = 0; r < 4; r++) {
                int row = m0 + wm * 32 + mi * 16 + (lane >> 2) + (r >= 2 ? 8 : 0);
                int col = n0 + wn * 32 + ni * 8 + 2 * (lane & 3) + (r & 1);
                float val = c[mi][ni][r] + bias[col];
                if (scatter) {
                    int bb = row / T_;
                    int t  = row - bb * T_;
                    int h  = col >> 6;
                    int dh = col & 63;
                    C[((size_t)(bb * H_ + h) * T_ + t) * DH_ + dh] = val;
                } else {
                    C[(size_t)row * D_ + col] = val;
                }
            }
        }
    }
}

// ---------------- V suffix sums per (b,h): VS[t] = sum_{j>t} V[j] ----------------
// Two-pass chunked scan: (a) local suffix within 64-row chunks + chunk totals,
// (b) add suffix-of-chunk-totals.
__global__ __launch_bounds__(64)
void vsuffix_a()
{
    const int bh = blockIdx.y;                 // 0..23
    const int ch = blockIdx.x;                 // 0..31
    const int d  = threadIdx.x;                // 0..63
    const float* V = g_V  + (size_t)bh * T_ * DH_;
    float*       S = g_VS + (size_t)bh * T_ * DH_;
    const int t0 = ch * 64;
    float sum = 0.f;
#pragma unroll 8
    for (int t = t0 + 63; t >= t0; t--) {
        S[(size_t)t * DH_ + d] = sum;
        sum += V[(size_t)t * DH_ + d];
    }
    g_CT[((size_t)bh * 32 + ch) * DH_ + d] = sum;
}

__global__ __launch_bounds__(64)
void vsuffix_b()
{
    const int bh = blockIdx.y;
    const int ch = blockIdx.x;
    const int d  = threadIdx.x;
    if (ch == 31) return;
    float off = 0.f;
    for (int cc = ch + 1; cc < 32; cc++)
        off += g_CT[((size_t)bh * 32 + cc) * DH_ + d];
    float* S = g_VS + (size_t)bh * T_ * DH_;
    const int t0 = ch * 64;
#pragma unroll 8
    for (int t = t0; t < t0 + 64; t++)
        S[(size_t)t * DH_ + d] += off;
}

// ---------------- fused causal attention (zero-fill semantics) -------------------
// grid (32 q-tiles, 24 bh), block (16,16). Dynamic smem.
#define QS(r,c) Qs[(r) * 65 + (c)]
#define KS(r,c) Ks[(r) * 65 + (c)]
#define VT(r,c) Vt[(r) * 65 + (c)]
#define PS(r,c) Ps[(r) * 68 + (c)]

__global__ __launch_bounds__(256)
void attn_kernel()
{
    extern __shared__ float sm[];
    float* Qs = sm;                 // 64 x 65
    float* Ks = sm + 4160;          // 64 x 65
    float* Vt = sm + 8320;          // 64 x 65
    float* Ps = sm + 12480;         // 64 x 68

    const int tx = threadIdx.x, ty = threadIdx.y;
    const int tid = ty * 16 + tx;
    const int bh = blockIdx.y;
    const int qt = blockIdx.x;
    const int q0 = qt * 64;

    const float* Q    = g_Q  + (size_t)bh * T_ * DH_;
    const float* K    = g_K  + (size_t)bh * T_ * DH_;
    const float* V    = g_V  + (size_t)bh * T_ * DH_;
    const float* Vsuf = g_VS + (size_t)bh * T_ * DH_;

#pragma unroll
    for (int r = 0; r < 4; r++) {
        int idx = tid + r * 256;
        int row = idx >> 4;
        int q4  = idx & 15;
        float4 v = *(const float4*)(Q + (size_t)(q0 + row) * DH_ + q4 * 4);
        QS(row, q4 * 4 + 0) = v.x; QS(row, q4 * 4 + 1) = v.y;
        QS(row, q4 * 4 + 2) = v.z; QS(row, q4 * 4 + 3) = v.w;
    }

    float o[4][4];
    float rsum[4];
#pragma unroll
    for (int i = 0; i < 4; i++) {
        rsum[i] = 0.f;
#pragma unroll
        for (int j = 0; j < 4; j++) o[i][j] = 0.f;
    }

    for (int kt = 0; kt <= qt; kt++) {
        __syncthreads();
#pragma unroll
        for (int r = 0; r < 4; r++) {
            int idx = tid + r * 256;
            int row = idx >> 4;
            int q4  = idx & 15;
            float4 vk = *(const float4*)(K + (size_t)(kt * 64 + row) * DH_ + q4 * 4);
            KS(row, q4 * 4 + 0) = vk.x; KS(row, q4 * 4 + 1) = vk.y;
            KS(row, q4 * 4 + 2) = vk.z; KS(row, q4 * 4 + 3) = vk.w;
            float4 vv = *(const float4*)(V + (size_t)(kt * 64 + row) * DH_ + q4 * 4);
            VT(row, q4 * 4 + 0) = vv.x; VT(row, q4 * 4 + 1) = vv.y;
            VT(row, q4 * 4 + 2) = vv.z; VT(row, q4 * 4 + 3) = vv.w;
        }
        __syncthreads();

        float s[4][4];
#pragma unroll
        for (int i = 0; i < 4; i++)
#pragma unroll
            for (int j = 0; j < 4; j++) s[i][j] = 0.f;

#pragma unroll 16
        for (int k = 0; k < 64; k++) {
            float a[4], b[4];
#pragma unroll
            for (int i = 0; i < 4; i++) a[i] = QS(ty * 4 + i, k);
#pragma unroll
            for (int j = 0; j < 4; j++) b[j] = KS(tx * 4 + j, k);
#pragma unroll
            for (int i = 0; i < 4; i++)
#pragma unroll
                for (int j = 0; j < 4; j++) s[i][j] = fmaf(a[i], b[j], s[i][j]);
        }

        const bool diag = (kt == qt);
#pragma unroll
        for (int i = 0; i < 4; i++) {
            int qi = q0 + ty * 4 + i;
#pragma unroll
            for (int j = 0; j < 4; j++) {
                int key = kt * 64 + tx * 4 + j;
                float p = (diag && key > qi) ? 0.f : __expf(s[i][j] * 0.125f);
                rsum[i] += p;
                PS(ty * 4 + i, tx * 4 + j) = p;
            }
        }
        __syncthreads();

#pragma unroll 16
        for (int k = 0; k < 64; k++) {
            float a[4], b[4];
#pragma unroll
            for (int i = 0; i < 4; i++) a[i] = PS(ty * 4 + i, k);
#pragma unroll
            for (int j = 0; j < 4; j++) b[j] = VT(k, tx * 4 + j);
#pragma unroll
            for (int i = 0; i < 4; i++)
#pragma unroll
                for (int j = 0; j < 4; j++) o[i][j] = fmaf(a[i], b[j], o[i][j]);
        }
    }

#pragma unroll
    for (int i = 0; i < 4; i++) {
        float r = rsum[i];
        r += __shfl_xor_sync(0xffffffffu, r, 1);
        r += __shfl_xor_sync(0xffffffffu, r, 2);
        r += __shfl_xor_sync(0xffffffffu, r, 4);
        r += __shfl_xor_sync(0xffffffffu, r, 8);
        rsum[i] = r;
    }

    const int b = bh / H_;
    const int h = bh - b * H_;
#pragma unroll
    for (int i = 0; i < 4; i++) {
        int qi = q0 + ty * 4 + i;
        float denom = rsum[i] + (float)(T_ - 1 - qi);
        float inv = 1.f / denom;
#pragma unroll
        for (int j = 0; j < 4; j++) {
            int dh = tx * 4 + j;
            float num = o[i][j] + Vsuf[(size_t)qi * DH_ + dh];
            g_AO[((size_t)(b * T_ + qi)) * D_ + h * DH_ + dh] = num * inv;
        }
    }
}

// ---------------- launch -----------------
extern "C" void kernel_launch(void* const* d_in, const int* in_sizes, int n_in,
                              void* d_out, int out_size)
{
    const float* X  = (const float*)d_in[0];
    const float* Wq = (const float*)d_in[1];
    const float* bq = (const float*)d_in[2];
    const float* Wk = (const float*)d_in[3];
    const float* bk = (const float*)d_in[4];
    const float* Wv = (const float*)d_in[5];
    const float* bv = (const float*)d_in[6];
    const float* Wo = (const float*)d_in[7];
    const float* bo = (const float*)d_in[8];
    float* out = (float*)d_out;

    const int ATTN_SMEM = (64 * 65 * 3 + 64 * 68) * 4;   // 67328 B
    cudaFuncSetAttribute(attn_kernel, cudaFuncAttributeMaxDynamicSharedMemorySize, ATTN_SMEM);

    float* Qp;  cudaGetSymbolAddress((void**)&Qp,  g_Q);
    float* Kp;  cudaGetSymbolAddress((void**)&Kp,  g_K);
    float* Vp;  cudaGetSymbolAddress((void**)&Vp,  g_V);
    float* AOp; cudaGetSymbolAddress((void**)&AOp, g_AO);

    dim3 gblk(256);
    dim3 ggrid(D_ / 64, M_ / 128);    // (12, 32)

    gemm_tc<<<ggrid, gblk>>>(X, Wq, bq, Qp, 1);
    gemm_tc<<<ggrid, gblk>>>(X, Wk, bk, Kp, 1);
    gemm_tc<<<ggrid, gblk>>>(X, Wv, bv, Vp, 1);
    vsuffix_a<<<dim3(32, 24), 64>>>();
    vsuffix_b<<<dim3(32, 24), 64>>>();
    attn_kernel<<<dim3(T_ / 64, B_ * H_), dim3(16, 16), ATTN_SMEM>>>();
    gemm_tc<<<ggrid, gblk>>>(AOp, Wo, bo, out, 0);
}

// round 3
// speedup vs baseline: 3.1498x; 1.9189x over previous
#include <cuda_runtime.h>
#include <cuda_bf16.h>
#include <cstdint>

#define B_   2
#define T_   2048
#define D_   768
#define H_   12
#define DH_  64
#define M_   (B_ * T_)   // 4096

// ---------------- scratch (static device globals; no allocation) ----------------
__device__ float g_Q [B_ * H_ * T_ * DH_];   // [B,H,T,Dh]
__device__ float g_K [B_ * H_ * T_ * DH_];
__device__ float g_V [B_ * H_ * T_ * DH_];
__device__ float g_VS[B_ * H_ * T_ * DH_];   // suffix sums of V
__device__ float g_AO[M_ * D_];              // attention out, [B,T, H*Dh]
__device__ float g_CT[24 * 32 * DH_];        // per-chunk V totals

// ---------------- tf32 helpers ----------------
__device__ __forceinline__ uint32_t f2tf32(float x) {
    uint32_t u;
    asm("cvt.rna.tf32.f32 %0, %1;" : "=r"(u) : "f"(x));
    return u;
}

#define MMA_TF32(c, a, b)                                                        \
    asm volatile(                                                                \
        "mma.sync.aligned.m16n8k8.row.col.f32.tf32.tf32.f32 "                    \
        "{%0,%1,%2,%3},{%4,%5,%6,%7},{%8,%9},{%0,%1,%2,%3};"                     \
        : "+f"((c)[0]), "+f"((c)[1]), "+f"((c)[2]), "+f"((c)[3])                 \
        : "r"((a)[0]), "r"((a)[1]), "r"((a)[2]), "r"((a)[3]),                    \
          "r"((b)[0]), "r"((b)[1]))

// ---------------- tensor-core GEMM body (shared by QKV-fused and O-proj) --------
__device__ __forceinline__
void gemm_body(const float* __restrict__ A, const float* __restrict__ W,
               const float* __restrict__ bias, float* __restrict__ C, int scatter)
{
    __shared__ float As[128][36];
    __shared__ float Ws[32][72];

    const int tid  = threadIdx.x;
    const int lane = tid & 31;
    const int wid  = tid >> 5;
    const int wm   = wid & 3;
    const int wn   = wid >> 2;
    const int m0   = blockIdx.y * 128;
    const int n0   = blockIdx.x * 64;

    float c[2][4][4];
#pragma unroll
    for (int mi = 0; mi < 2; mi++)
#pragma unroll
        for (int ni = 0; ni < 4; ni++)
#pragma unroll
            for (int r = 0; r < 4; r++) c[mi][ni][r] = 0.f;

    for (int kk = 0; kk < D_; kk += 32) {
#pragma unroll
        for (int r = 0; r < 4; r++) {
            int idx = tid + r * 256;
            int row = idx >> 3;
            int c4  = idx & 7;
            float4 v = *(const float4*)(A + (size_t)(m0 + row) * D_ + kk + c4 * 4);
            *(float4*)&As[row][c4 * 4] = v;
        }
#pragma unroll
        for (int r = 0; r < 2; r++) {
            int idx = tid + r * 256;
            int kr  = idx >> 4;
            int c4  = idx & 15;
            float4 v = *(const float4*)(W + (size_t)(kk + kr) * D_ + n0 + c4 * 4);
            *(float4*)&Ws[kr][c4 * 4] = v;
        }
        __syncthreads();

#pragma unroll
        for (int ks = 0; ks < 4; ks++) {
            const int k0 = ks * 8;
            uint32_t a[2][4], b[4][2];
            const int ac = k0 + (lane & 3);
#pragma unroll
            for (int mi = 0; mi < 2; mi++) {
                int ar = wm * 32 + mi * 16 + (lane >> 2);
                a[mi][0] = f2tf32(As[ar][ac]);
                a[mi][1] = f2tf32(As[ar + 8][ac]);
                a[mi][2] = f2tf32(As[ar][ac + 4]);
                a[mi][3] = f2tf32(As[ar + 8][ac + 4]);
            }
#pragma unroll
            for (int ni = 0; ni < 4; ni++) {
                int col = wn * 32 + ni * 8 + (lane >> 2);
                b[ni][0] = f2tf32(Ws[k0 + (lane & 3)][col]);
                b[ni][1] = f2tf32(Ws[k0 + 4 + (lane & 3)][col]);
            }
#pragma unroll
            for (int mi = 0; mi < 2; mi++)
#pragma unroll
                for (int ni = 0; ni < 4; ni++)
                    MMA_TF32(c[mi][ni], a[mi], b[ni]);
        }
        __syncthreads();
    }

#pragma unroll
    for (int mi = 0; mi < 2; mi++) {
#pragma unroll
        for (int ni = 0; ni < 4; ni++) {
#pragma unroll
            for (int r = 0; r < 4; r++) {
                int row = m0 + wm * 32 + mi * 16 + (lane >> 2) + (r >= 2 ? 8 : 0);
                int col = n0 + wn * 32 + ni * 8 + 2 * (lane & 3) + (r & 1);
                float val = c[mi][ni][r] + bias[col];
                if (scatter) {
                    int bb = row / T_;
                    int t  = row - bb * T_;
                    int h  = col >> 6;
                    int dh = col & 63;
                    C[((size_t)(bb * H_ + h) * T_ + t) * DH_ + dh] = val;
                } else {
                    C[(size_t)row * D_ + col] = val;
                }
            }
        }
    }
}

// Fused Q/K/V projections: blockIdx.z selects the matrix.
__global__ __launch_bounds__(256)
void gemm_qkv(const float* __restrict__ X,
              const float* __restrict__ Wq, const float* __restrict__ bq,
              const float* __restrict__ Wk, const float* __restrict__ bk,
              const float* __restrict__ Wv, const float* __restrict__ bv,
              float* __restrict__ Qp, float* __restrict__ Kp, float* __restrict__ Vp)
{
    const int z = blockIdx.z;
    const float* W = (z == 0) ? Wq : (z == 1) ? Wk : Wv;
    const float* b = (z == 0) ? bq : (z == 1) ? bk : bv;
    float*       C = (z == 0) ? Qp : (z == 1) ? Kp : Vp;
    gemm_body(X, W, b, C, 1);
}

__global__ __launch_bounds__(256)
void gemm_out(const float* __restrict__ A, const float* __restrict__ W,
              const float* __restrict__ bias, float* __restrict__ C)
{
    gemm_body(A, W, bias, C, 0);
}

// ---------------- V suffix sums per (b,h): VS[t] = sum_{j>t} V[j] ----------------
__global__ __launch_bounds__(64)
void vsuffix_a()
{
    const int bh = blockIdx.y;
    const int ch = blockIdx.x;
    const int d  = threadIdx.x;
    const float* V = g_V  + (size_t)bh * T_ * DH_;
    float*       S = g_VS + (size_t)bh * T_ * DH_;
    const int t0 = ch * 64;
    float sum = 0.f;
#pragma unroll 16
    for (int t = t0 + 63; t >= t0; t--) {
        S[(size_t)t * DH_ + d] = sum;
        sum += V[(size_t)t * DH_ + d];
    }
    g_CT[((size_t)bh * 32 + ch) * DH_ + d] = sum;
}

__global__ __launch_bounds__(64)
void vsuffix_b()
{
    const int bh = blockIdx.y;
    const int ch = blockIdx.x;
    const int d  = threadIdx.x;
    if (ch == 31) return;
    float off = 0.f;
#pragma unroll 8
    for (int cc = ch + 1; cc < 32; cc++)
        off += g_CT[((size_t)bh * 32 + cc) * DH_ + d];
    float* S = g_VS + (size_t)bh * T_ * DH_;
    const int t0 = ch * 64;
#pragma unroll 16
    for (int t = t0; t < t0 + 64; t++)
        S[(size_t)t * DH_ + d] += off;
}

// ---------------- tensor-core causal attention (zero-fill semantics) -------------
// grid (32 q-tiles reversed, 24 bh), 256 threads = 8 warps: 4(m16-groups... m) x 2(n32).
// smem: Q,K,P padded 68 (A/B frag bank = 4r+c), V padded 72 (bank = 8k+r).
#define AQ(r,c) Qs[(r) * 68 + (c)]
#define AK(r,c) Ks[(r) * 68 + (c)]
#define AV(r,c) Vs[(r) * 72 + (c)]
#define AP(r,c) Ps[(r) * 68 + (c)]

#define ATT_SMEM ((64 * 68 * 3 + 64 * 72 + 128) * 4)

__global__ __launch_bounds__(256, 2)
void attn_tc()
{
    extern __shared__ uint32_t smbuf[];
    uint32_t* Qs = smbuf;                 // 64 x 68
    uint32_t* Ks = Qs + 64 * 68;
    uint32_t* Vs = Ks + 64 * 68;          // 64 x 72
    uint32_t* Ps = Vs + 64 * 72;          // 64 x 68
    float*    rs = (float*)(Ps + 64 * 68);   // [2][64] per-n-slab row sums

    const int tid  = threadIdx.x;
    const int lane = tid & 31;
    const int wid  = tid >> 5;
    const int wm   = wid & 3;            // m slab: rows wm*16 .. +15
    const int wn   = wid >> 2;           // n slab: cols wn*32 .. +31
    const int bh   = blockIdx.y;
    const int qt   = gridDim.x - 1 - blockIdx.x;   // heavy tiles first
    const int q0   = qt * 64;

    const float* Q    = g_Q  + (size_t)bh * T_ * DH_;
    const float* K    = g_K  + (size_t)bh * T_ * DH_;
    const float* V    = g_V  + (size_t)bh * T_ * DH_;
    const float* Vsuf = g_VS + (size_t)bh * T_ * DH_;

    // load + convert Q tile
#pragma unroll
    for (int r = 0; r < 4; r++) {
        int idx = tid + r * 256;
        int row = idx >> 4;
        int c4  = (idx & 15) * 4;
        float4 v = *(const float4*)(Q + (size_t)(q0 + row) * DH_ + c4);
        AQ(row, c4 + 0) = f2tf32(v.x); AQ(row, c4 + 1) = f2tf32(v.y);
        AQ(row, c4 + 2) = f2tf32(v.z); AQ(row, c4 + 3) = f2tf32(v.w);
    }

    float o[4][4];
#pragma unroll
    for (int ni = 0; ni < 4; ni++)
#pragma unroll
        for (int r = 0; r < 4; r++) o[ni][r] = 0.f;
    float rsum0 = 0.f, rsum1 = 0.f;

    const int gr = lane >> 2;      // 0..7
    const int gc = lane & 3;       // 0..3

    for (int kt = 0; kt <= qt; kt++) {
        __syncthreads();           // prior PV reads of Ks/Vs/Ps complete
        // load + convert K,V tiles
#pragma unroll
        for (int r = 0; r < 4; r++) {
            int idx = tid + r * 256;
            int row = idx >> 4;
            int c4  = (idx & 15) * 4;
            float4 vk = *(const float4*)(K + (size_t)(kt * 64 + row) * DH_ + c4);
            AK(row, c4 + 0) = f2tf32(vk.x); AK(row, c4 + 1) = f2tf32(vk.y);
            AK(row, c4 + 2) = f2tf32(vk.z); AK(row, c4 + 3) = f2tf32(vk.w);
            float4 vv = *(const float4*)(V + (size_t)(kt * 64 + row) * DH_ + c4);
            AV(row, c4 + 0) = f2tf32(vv.x); AV(row, c4 + 1) = f2tf32(vv.y);
            AV(row, c4 + 2) = f2tf32(vv.z); AV(row, c4 + 3) = f2tf32(vv.w);
        }
        __syncthreads();

        // ---- S = Q . K^T ----
        float s[4][4];
#pragma unroll
        for (int ni = 0; ni < 4; ni++)
#pragma unroll
            for (int r = 0; r < 4; r++) s[ni][r] = 0.f;

#pragma unroll
        for (int ks = 0; ks < 8; ks++) {
            const int k0 = ks * 8;
            uint32_t a[4], b[4][2];
            int ar = wm * 16 + gr;
            int ac = k0 + gc;
            a[0] = AQ(ar, ac);     a[1] = AQ(ar + 8, ac);
            a[2] = AQ(ar, ac + 4); a[3] = AQ(ar + 8, ac + 4);
#pragma unroll
            for (int ni = 0; ni < 4; ni++) {
                int key = wn * 32 + ni * 8 + gr;
                b[ni][0] = AK(key, k0 + gc);
                b[ni][1] = AK(key, k0 + 4 + gc);
            }
#pragma unroll
            for (int ni = 0; ni < 4; ni++)
                MMA_TF32(s[ni], a, b[ni]);
        }

        // ---- exp + diagonal mask + rowsum + stage P (tf32) ----
        const bool diag = (kt == qt);
        const int rl = wm * 16 + gr;
        const int row0 = q0 + rl;
#pragma unroll
        for (int ni = 0; ni < 4; ni++) {
            int cl   = wn * 32 + ni * 8 + 2 * gc;
            int colg = kt * 64 + cl;
            float p0 = (diag && colg     > row0) ? 0.f : __expf(s[ni][0] * 0.125f);
            float p1 = (diag && colg + 1 > row0) ? 0.f : __expf(s[ni][1] * 0.125f);
            float p2 = (diag && colg     > row0 + 8) ? 0.f : __expf(s[ni][2] * 0.125f);
            float p3 = (diag && colg + 1 > row0 + 8) ? 0.f : __expf(s[ni][3] * 0.125f);
            rsum0 += p0 + p1;
            rsum1 += p2 + p3;
            uint2 w0 = make_uint2(f2tf32(p0), f2tf32(p1));
            uint2 w1 = make_uint2(f2tf32(p2), f2tf32(p3));
            *(uint2*)&AP(rl, cl)     = w0;
            *(uint2*)&AP(rl + 8, cl) = w1;
        }
        __syncthreads();

        // ---- O += P . V ----
#pragma unroll
        for (int ks = 0; ks < 8; ks++) {
            const int k0 = ks * 8;
            uint32_t a[4], b[4][2];
            int ar = wm * 16 + gr;
            int ac = k0 + gc;
            a[0] = AP(ar, ac);     a[1] = AP(ar + 8, ac);
            a[2] = AP(ar, ac + 4); a[3] = AP(ar + 8, ac + 4);
#pragma unroll
            for (int ni = 0; ni < 4; ni++) {
                int dh = wn * 32 + ni * 8 + gr;
                b[ni][0] = AV(k0 + gc, dh);
                b[ni][1] = AV(k0 + 4 + gc, dh);
            }
#pragma unroll
            for (int ni = 0; ni < 4; ni++)
                MMA_TF32(o[ni], a, b[ni]);
        }
    }

    // ---- final rowsum reduction: within quad, then across the 2 n-slab warps ----
    rsum0 += __shfl_xor_sync(0xffffffffu, rsum0, 1);
    rsum0 += __shfl_xor_sync(0xffffffffu, rsum0, 2);
    rsum1 += __shfl_xor_sync(0xffffffffu, rsum1, 1);
    rsum1 += __shfl_xor_sync(0xffffffffu, rsum1, 2);
    if ((lane & 3) == 0) {
        rs[wn * 64 + wm * 16 + gr]     = rsum0;
        rs[wn * 64 + wm * 16 + 8 + gr] = rsum1;
    }
    __syncthreads();

    // ---- epilogue ----
    const int b = bh / H_;
    const int h = bh - b * H_;
#pragma unroll
    for (int half = 0; half < 2; half++) {
        int rl = wm * 16 + gr + 8 * half;
        int qi = q0 + rl;
        float denom = rs[rl] + rs[64 + rl] + (float)(T_ - 1 - qi);
        float inv = 1.f / denom;
        float* dst = g_AO + ((size_t)(b * T_ + qi)) * D_ + h * DH_;
        const float* vs = Vsuf + (size_t)qi * DH_;
#pragma unroll
        for (int ni = 0; ni < 4; ni++) {
            int cl = wn * 32 + ni * 8 + 2 * gc;
            dst[cl]     = (o[ni][half * 2 + 0] + vs[cl])     * inv;
            dst[cl + 1] = (o[ni][half * 2 + 1] + vs[cl + 1]) * inv;
        }
    }
}

// ---------------- launch -----------------
extern "C" void kernel_launch(void* const* d_in, const int* in_sizes, int n_in,
                              void* d_out, int out_size)
{
    const float* X  = (const float*)d_in[0];
    const float* Wq = (const float*)d_in[1];
    const float* bq = (const float*)d_in[2];
    const float* Wk = (const float*)d_in[3];
    const float* bk = (const float*)d_in[4];
    const float* Wv = (const float*)d_in[5];
    const float* bv = (const float*)d_in[6];
    const float* Wo = (const float*)d_in[7];
    const float* bo = (const float*)d_in[8];
    float* out = (float*)d_out;

    cudaFuncSetAttribute(attn_tc, cudaFuncAttributeMaxDynamicSharedMemorySize, ATT_SMEM);

    float* Qp;  cudaGetSymbolAddress((void**)&Qp,  g_Q);
    float* Kp;  cudaGetSymbolAddress((void**)&Kp,  g_K);
    float* Vp;  cudaGetSymbolAddress((void**)&Vp,  g_V);
    float* AOp; cudaGetSymbolAddress((void**)&AOp, g_AO);

    gemm_qkv<<<dim3(D_ / 64, M_ / 128, 3), 256>>>(X, Wq, bq, Wk, bk, Wv, bv, Qp, Kp, Vp);
    vsuffix_a<<<dim3(32, 24), 64>>>();
    vsuffix_b<<<dim3(32, 24), 64>>>();
    attn_tc<<<dim3(T_ / 64, B_ * H_), 256, ATT_SMEM>>>();
    gemm_out<<<dim3(D_ / 64, M_ / 128), 256>>>(AOp, Wo, bo, out);
}

// round 4
// speedup vs baseline: 3.9710x; 1.2607x over previous
#include <cuda_runtime.h>
#include <cuda_fp16.h>
#include <cuda_bf16.h>
#include <cstdint>

#define B_   2
#define T_   2048
#define D_   768
#define H_   12
#define DH_  64
#define M_   (B_ * T_)   // 4096

// ---------------- scratch (static device globals; no allocation) ----------------
__device__ float g_Q [B_ * H_ * T_ * DH_];   // [B,H,T,Dh]
__device__ float g_K [B_ * H_ * T_ * DH_];
__device__ float g_V [B_ * H_ * T_ * DH_];
__device__ float g_VS[B_ * H_ * T_ * DH_];   // suffix sums of V
__device__ float g_AO[M_ * D_];              // attention out, [B,T, H*Dh]
__device__ float g_CT[24 * 32 * DH_];        // per-chunk V totals

// ---------------- mma helpers ----------------
__device__ __forceinline__ uint32_t f2tf32(float x) {
    uint32_t u;
    asm("cvt.rna.tf32.f32 %0, %1;" : "=r"(u) : "f"(x));
    return u;
}

#define MMA_TF32(c, a, b)                                                        \
    asm volatile(                                                                \
        "mma.sync.aligned.m16n8k8.row.col.f32.tf32.tf32.f32 "                    \
        "{%0,%1,%2,%3},{%4,%5,%6,%7},{%8,%9},{%0,%1,%2,%3};"                     \
        : "+f"((c)[0]), "+f"((c)[1]), "+f"((c)[2]), "+f"((c)[3])                 \
        : "r"((a)[0]), "r"((a)[1]), "r"((a)[2]), "r"((a)[3]),                    \
          "r"((b)[0]), "r"((b)[1]))

#define MMA_F16(c, a, b)                                                         \
    asm volatile(                                                                \
        "mma.sync.aligned.m16n8k16.row.col.f32.f16.f16.f32 "                     \
        "{%0,%1,%2,%3},{%4,%5,%6,%7},{%8,%9},{%0,%1,%2,%3};"                     \
        : "+f"((c)[0]), "+f"((c)[1]), "+f"((c)[2]), "+f"((c)[3])                 \
        : "r"((a)[0]), "r"((a)[1]), "r"((a)[2]), "r"((a)[3]),                    \
          "r"((b)[0]), "r"((b)[1]))

__device__ __forceinline__ void ldmx4(uint32_t* r, uint32_t addr) {
    asm volatile("ldmatrix.sync.aligned.m8n8.x4.shared.b16 {%0,%1,%2,%3}, [%4];"
                 : "=r"(r[0]), "=r"(r[1]), "=r"(r[2]), "=r"(r[3]) : "r"(addr));
}
__device__ __forceinline__ void ldmx4t(uint32_t* r, uint32_t addr) {
    asm volatile("ldmatrix.sync.aligned.m8n8.x4.trans.shared.b16 {%0,%1,%2,%3}, [%4];"
                 : "=r"(r[0]), "=r"(r[1]), "=r"(r[2]), "=r"(r[3]) : "r"(addr));
}
__device__ __forceinline__ uint32_t h2u(half2 h) { return *reinterpret_cast<uint32_t*>(&h); }

// ---------------- tensor-core GEMM body (tf32, unchanged) -----------------------
__device__ __forceinline__
void gemm_body(const float* __restrict__ A, const float* __restrict__ W,
               const float* __restrict__ bias, float* __restrict__ C, int scatter)
{
    __shared__ float As[128][36];
    __shared__ float Ws[32][72];

    const int tid  = threadIdx.x;
    const int lane = tid & 31;
    const int wid  = tid >> 5;
    const int wm   = wid & 3;
    const int wn   = wid >> 2;
    const int m0   = blockIdx.y * 128;
    const int n0   = blockIdx.x * 64;

    float c[2][4][4];
#pragma unroll
    for (int mi = 0; mi < 2; mi++)
#pragma unroll
        for (int ni = 0; ni < 4; ni++)
#pragma unroll
            for (int r = 0; r < 4; r++) c[mi][ni][r] = 0.f;

    for (int kk = 0; kk < D_; kk += 32) {
#pragma unroll
        for (int r = 0; r < 4; r++) {
            int idx = tid + r * 256;
            int row = idx >> 3;
            int c4  = idx & 7;
            float4 v = *(const float4*)(A + (size_t)(m0 + row) * D_ + kk + c4 * 4);
            *(float4*)&As[row][c4 * 4] = v;
        }
#pragma unroll
        for (int r = 0; r < 2; r++) {
            int idx = tid + r * 256;
            int kr  = idx >> 4;
            int c4  = idx & 15;
            float4 v = *(const float4*)(W + (size_t)(kk + kr) * D_ + n0 + c4 * 4);
            *(float4*)&Ws[kr][c4 * 4] = v;
        }
        __syncthreads();

#pragma unroll
        for (int ks = 0; ks < 4; ks++) {
            const int k0 = ks * 8;
            uint32_t a[2][4], b[4][2];
            const int ac = k0 + (lane & 3);
#pragma unroll
            for (int mi = 0; mi < 2; mi++) {
                int ar = wm * 32 + mi * 16 + (lane >> 2);
                a[mi][0] = f2tf32(As[ar][ac]);
                a[mi][1] = f2tf32(As[ar + 8][ac]);
                a[mi][2] = f2tf32(As[ar][ac + 4]);
                a[mi][3] = f2tf32(As[ar + 8][ac + 4]);
            }
#pragma unroll
            for (int ni = 0; ni < 4; ni++) {
                int col = wn * 32 + ni * 8 + (lane >> 2);
                b[ni][0] = f2tf32(Ws[k0 + (lane & 3)][col]);
                b[ni][1] = f2tf32(Ws[k0 + 4 + (lane & 3)][col]);
            }
#pragma unroll
            for (int mi = 0; mi < 2; mi++)
#pragma unroll
                for (int ni = 0; ni < 4; ni++)
                    MMA_TF32(c[mi][ni], a[mi], b[ni]);
        }
        __syncthreads();
    }

#pragma unroll
    for (int mi = 0; mi < 2; mi++) {
#pragma unroll
        for (int ni = 0; ni < 4; ni++) {
#pragma unroll
            for (int r = 0; r < 4; r++) {
                int row = m0 + wm * 32 + mi * 16 + (lane >> 2) + (r >= 2 ? 8 : 0);
                int col = n0 + wn * 32 + ni * 8 + 2 * (lane & 3) + (r & 1);
                float val = c[mi][ni][r] + bias[col];
                if (scatter) {
                    int bb = row / T_;
                    int t  = row - bb * T_;
                    int h  = col >> 6;
                    int dh = col & 63;
                    C[((size_t)(bb * H_ + h) * T_ + t) * DH_ + dh] = val;
                } else {
                    C[(size_t)row * D_ + col] = val;
                }
            }
        }
    }
}

__global__ __launch_bounds__(256)
void gemm_qkv(const float* __restrict__ X,
              const float* __restrict__ Wq, const float* __restrict__ bq,
              const float* __restrict__ Wk, const float* __restrict__ bk,
              const float* __restrict__ Wv, const float* __restrict__ bv,
              float* __restrict__ Qp, float* __restrict__ Kp, float* __restrict__ Vp)
{
    const int z = blockIdx.z;
    const float* W = (z == 0) ? Wq : (z == 1) ? Wk : Wv;
    const float* b = (z == 0) ? bq : (z == 1) ? bk : bv;
    float*       C = (z == 0) ? Qp : (z == 1) ? Kp : Vp;
    gemm_body(X, W, b, C, 1);
}

__global__ __launch_bounds__(256)
void gemm_out(const float* __restrict__ A, const float* __restrict__ W,
              const float* __restrict__ bias, float* __restrict__ C)
{
    gemm_body(A, W, bias, C, 0);
}

// ---------------- V suffix sums ----------------
__global__ __launch_bounds__(64)
void vsuffix_a()
{
    const int bh = blockIdx.y;
    const int ch = blockIdx.x;
    const int d  = threadIdx.x;
    const float* V = g_V  + (size_t)bh * T_ * DH_;
    float*       S = g_VS + (size_t)bh * T_ * DH_;
    const int t0 = ch * 64;
    float sum = 0.f;
#pragma unroll 16
    for (int t = t0 + 63; t >= t0; t--) {
        S[(size_t)t * DH_ + d] = sum;
        sum += V[(size_t)t * DH_ + d];
    }
    g_CT[((size_t)bh * 32 + ch) * DH_ + d] = sum;
}

__global__ __launch_bounds__(64)
void vsuffix_b()
{
    const int bh = blockIdx.y;
    const int ch = blockIdx.x;
    const int d  = threadIdx.x;
    if (ch == 31) return;
    float off = 0.f;
#pragma unroll 8
    for (int cc = ch + 1; cc < 32; cc++)
        off += g_CT[((size_t)bh * 32 + cc) * DH_ + d];
    float* S = g_VS + (size_t)bh * T_ * DH_;
    const int t0 = ch * 64;
#pragma unroll 16
    for (int t = t0; t < t0 + 64; t++)
        S[(size_t)t * DH_ + d] += off;
}

// ---------------- fp16 tensor-core causal attention (FA2 style) -----------------
// 8 warps = 4 (m16 q-row groups) x 2 (32-key halves). P never touches smem.
#define LDH 72   // half-row stride (conflict-free ldmatrix: 144B = 4-bank shift/row)

__global__ __launch_bounds__(256, 2)
void attn_tc()
{
    __shared__ __align__(16) uint8_t smraw[3 * 64 * LDH * 2 + 4 * 16 * 64 * 4 + 64 * 4];
    half* Qh = (half*)smraw;
    half* Kh = Qh + 64 * LDH;
    half* Vh = Kh + 64 * LDH;
    float* redO = (float*)(smraw + 3 * 64 * LDH * 2);
    float* redS = redO + 4 * 16 * 64;

    const int tid  = threadIdx.x;
    const int lane = tid & 31;
    const int wid  = tid >> 5;
    const int wm   = wid & 3;            // q-row group: rows wm*16..+15
    const int wh   = wid >> 2;           // key half: keys wh*32..+31 of each tile
    const int gr   = lane >> 2;          // 0..7
    const int gc   = lane & 3;           // 0..3
    const int lrow = lane & 15;
    const int lcol = (lane >> 4) * 8;

    const int bh = blockIdx.y;
    const int qt = gridDim.x - 1 - blockIdx.x;    // heavy tiles first
    const int q0 = qt * 64;

    const float* Q    = g_Q  + (size_t)bh * T_ * DH_;
    const float* K    = g_K  + (size_t)bh * T_ * DH_;
    const float* V    = g_V  + (size_t)bh * T_ * DH_;
    const float* Vsuf = g_VS + (size_t)bh * T_ * DH_;

    // ---- load Q tile to smem (fp16), then hoist Q fragments into registers ----
#pragma unroll
    for (int r = 0; r < 1; r++) {
        int idx = tid;                    // 64 rows x 16 float4 = 1024; 4 per thread
#pragma unroll
        for (int rr = 0; rr < 4; rr++) {
            int i2  = idx + rr * 256;
            int row = i2 >> 4;
            int c4  = (i2 & 15) * 4;
            float4 v = *(const float4*)(Q + (size_t)(q0 + row) * DH_ + c4);
            half2 h0 = __floats2half2_rn(v.x, v.y);
            half2 h1 = __floats2half2_rn(v.z, v.w);
            uint2 u = make_uint2(h2u(h0), h2u(h1));
            *(uint2*)&Qh[row * LDH + c4] = u;
        }
    }
    __syncthreads();

    uint32_t qf[4][4];
    {
        uint32_t qaddr = (uint32_t)__cvta_generic_to_shared(
            &Qh[(wm * 16 + lrow) * LDH + lcol]);
#pragma unroll
        for (int ks = 0; ks < 4; ks++)
            ldmx4(qf[ks], qaddr + ks * 32);   // +16 halves per k-step
    }

    float o[8][4];
#pragma unroll
    for (int ni = 0; ni < 8; ni++)
#pragma unroll
        for (int r = 0; r < 4; r++) o[ni][r] = 0.f;
    float rsum0 = 0.f, rsum1 = 0.f;

    const uint32_t kaddr0 = (uint32_t)__cvta_generic_to_shared(
        &Kh[(wh * 32 + lrow) * LDH + lcol]);
    const uint32_t kaddr1 = kaddr0 + 16 * LDH * 2;
    const uint32_t vaddr0 = (uint32_t)__cvta_generic_to_shared(
        &Vh[(wh * 32 + lrow) * LDH + lcol]);
    const uint32_t vaddr1 = vaddr0 + 16 * LDH * 2;

    for (int kt = 0; kt <= qt; kt++) {
        __syncthreads();                  // prior iteration done reading Kh/Vh
        // ---- load K,V tile (fp16) ----
#pragma unroll
        for (int rr = 0; rr < 4; rr++) {
            int i2  = tid + rr * 256;
            int row = i2 >> 4;
            int c4  = (i2 & 15) * 4;
            const float* kp = K + (size_t)(kt * 64 + row) * DH_ + c4;
            float4 vk = *(const float4*)kp;
            float4 vv = *(const float4*)(V + (size_t)(kt * 64 + row) * DH_ + c4);
            uint2 uk = make_uint2(h2u(__floats2half2_rn(vk.x, vk.y)),
                                  h2u(__floats2half2_rn(vk.z, vk.w)));
            uint2 uv = make_uint2(h2u(__floats2half2_rn(vv.x, vv.y)),
                                  h2u(__floats2half2_rn(vv.z, vv.w)));
            *(uint2*)&Kh[row * LDH + c4] = uk;
            *(uint2*)&Vh[row * LDH + c4] = uv;
        }
        __syncthreads();

        // ---- S = Q . K^T over this warp's 32 keys ----
        float s[4][4];
#pragma unroll
        for (int j = 0; j < 4; j++)
#pragma unroll
            for (int r = 0; r < 4; r++) s[j][r] = 0.f;

#pragma unroll
        for (int ks = 0; ks < 4; ks++) {
            uint32_t r0[4], r1[4];
            ldmx4(r0, kaddr0 + ks * 32);
            ldmx4(r1, kaddr1 + ks * 32);
            uint32_t b0[2] = { r0[0], r0[2] };   // keys wh*32 + 0..7
            uint32_t b1[2] = { r0[1], r0[3] };   // keys +8..15
            uint32_t b2[2] = { r1[0], r1[2] };   // keys +16..23
            uint32_t b3[2] = { r1[1], r1[3] };   // keys +24..31
            MMA_F16(s[0], qf[ks], b0);
            MMA_F16(s[1], qf[ks], b1);
            MMA_F16(s[2], qf[ks], b2);
            MMA_F16(s[3], qf[ks], b3);
        }

        // ---- exp + diag mask + rowsum; pack P as fp16 A-fragments ----
        const bool diag = (kt == qt);
        const int row0 = q0 + wm * 16 + gr;
        uint32_t pl[4], ph[4];
#pragma unroll
        for (int j = 0; j < 4; j++) {
            int colg = kt * 64 + wh * 32 + j * 8 + 2 * gc;
            float p0 = (diag && colg     > row0)     ? 0.f : __expf(s[j][0] * 0.125f);
            float p1 = (diag && colg + 1 > row0)     ? 0.f : __expf(s[j][1] * 0.125f);
            float p2 = (diag && colg     > row0 + 8) ? 0.f : __expf(s[j][2] * 0.125f);
            float p3 = (diag && colg + 1 > row0 + 8) ? 0.f : __expf(s[j][3] * 0.125f);
            rsum0 += p0 + p1;
            rsum1 += p2 + p3;
            pl[j] = h2u(__floats2half2_rn(p0, p1));
            ph[j] = h2u(__floats2half2_rn(p2, p3));
        }

        // ---- O += P . V (k = this warp's 32 keys) ----
#pragma unroll
        for (int ks2 = 0; ks2 < 2; ks2++) {
            uint32_t a[4] = { pl[ks2 * 2], ph[ks2 * 2], pl[ks2 * 2 + 1], ph[ks2 * 2 + 1] };
            uint32_t vbase = (ks2 == 0) ? vaddr0 : vaddr1;
#pragma unroll
            for (int dg = 0; dg < 4; dg++) {
                uint32_t rv[4];
                ldmx4t(rv, vbase + dg * 32);          // +16 halves in dh
                uint32_t bA[2] = { rv[0], rv[1] };    // dh dg*16 .. +7
                uint32_t bB[2] = { rv[2], rv[3] };    // dh dg*16+8 .. +15
                MMA_F16(o[dg * 2],     a, bA);
                MMA_F16(o[dg * 2 + 1], a, bB);
            }
        }
    }

    // ---- rowsum reduce over gc lanes ----
    rsum0 += __shfl_xor_sync(0xffffffffu, rsum0, 1);
    rsum0 += __shfl_xor_sync(0xffffffffu, rsum0, 2);
    rsum1 += __shfl_xor_sync(0xffffffffu, rsum1, 1);
    rsum1 += __shfl_xor_sync(0xffffffffu, rsum1, 2);

    __syncthreads();                      // Kh/Vh dead; redO/redS region live
    if (wh == 0) {
        if (gc == 0) {
            redS[wm * 16 + gr]     = rsum0;
            redS[wm * 16 + 8 + gr] = rsum1;
        }
#pragma unroll
        for (int ni = 0; ni < 8; ni++) {
            int c = ni * 8 + 2 * gc;
            *(float2*)&redO[(wm * 16 + gr) * 64 + c]     = make_float2(o[ni][0], o[ni][1]);
            *(float2*)&redO[(wm * 16 + 8 + gr) * 64 + c] = make_float2(o[ni][2], o[ni][3]);
        }
    }
    __syncthreads();

    if (wh == 1) {
        const int b = bh / H_;
        const int h = bh - b * H_;
#pragma unroll
        for (int half_ = 0; half_ < 2; half_++) {
            int rl = wm * 16 + gr + 8 * half_;
            int qi = q0 + rl;
            float own = (half_ == 0) ? rsum0 : rsum1;
            float denom = own + redS[rl] + (float)(T_ - 1 - qi);
            float inv = 1.f / denom;
            float* dst = g_AO + ((size_t)(b * T_ + qi)) * D_ + h * DH_;
            const float* vs = Vsuf + (size_t)qi * DH_;
#pragma unroll
            for (int ni = 0; ni < 8; ni++) {
                int c = ni * 8 + 2 * gc;
                float2 red = *(const float2*)&redO[rl * 64 + c];
                float2 vsv = *(const float2*)&vs[c];
                float v0 = (o[ni][half_ * 2 + 0] + red.x + vsv.x) * inv;
                float v1 = (o[ni][half_ * 2 + 1] + red.y + vsv.y) * inv;
                *(float2*)&dst[c] = make_float2(v0, v1);
            }
        }
    }
}

// ---------------- launch -----------------
extern "C" void kernel_launch(void* const* d_in, const int* in_sizes, int n_in,
                              void* d_out, int out_size)
{
    const float* X  = (const float*)d_in[0];
    const float* Wq = (const float*)d_in[1];
    const float* bq = (const float*)d_in[2];
    const float* Wk = (const float*)d_in[3];
    const float* bk = (const float*)d_in[4];
    const float* Wv = (const float*)d_in[5];
    const float* bv = (const float*)d_in[6];
    const float* Wo = (const float*)d_in[7];
    const float* bo = (const float*)d_in[8];
    float* out = (float*)d_out;

    float* Qp;  cudaGetSymbolAddress((void**)&Qp,  g_Q);
    float* Kp;  cudaGetSymbolAddress((void**)&Kp,  g_K);
    float* Vp;  cudaGetSymbolAddress((void**)&Vp,  g_V);
    float* AOp; cudaGetSymbolAddress((void**)&AOp, g_AO);

    gemm_qkv<<<dim3(D_ / 64, M_ / 128, 3), 256>>>(X, Wq, bq, Wk, bk, Wv, bv, Qp, Kp, Vp);
    vsuffix_a<<<dim3(32, 24), 64>>>();
    vsuffix_b<<<dim3(32, 24), 64>>>();
    attn_tc<<<dim3(T_ / 64, B_ * H_), 256>>>();
    gemm_out<<<dim3(D_ / 64, M_ / 128), 256>>>(AOp, Wo, bo, out);
}

// round 6
// speedup vs baseline: 6.3176x; 1.5909x over previous
#include <cuda_runtime.h>
#include <cuda_fp16.h>
#include <cstdint>

#define B_   2
#define T_   2048
#define D_   768
#define H_   12
#define DH_  64
#define M_   (B_ * T_)   // 4096

// ---------------- scratch (static device globals; no allocation) ----------------
__device__ half  g_Xh [M_ * D_];             // X in fp16
__device__ half  g_Wqh[D_ * D_];
__device__ half  g_Wkh[D_ * D_];
__device__ half  g_Wvh[D_ * D_];
__device__ half  g_Woh[D_ * D_];
__device__ half  g_Qh [B_ * H_ * T_ * DH_];  // [B,H,T,Dh] fp16
__device__ half  g_Kh [B_ * H_ * T_ * DH_];
__device__ half  g_Vh [B_ * H_ * T_ * DH_];
__device__ float g_VS [B_ * H_ * T_ * DH_];  // suffix sums of V (fp32)
__device__ half  g_AOh[M_ * D_];             // attention out, [B,T, H*Dh] fp16
__device__ float g_CT [24 * 64 * DH_];       // per-chunk V totals

// ---------------- helpers ----------------
#define MMA_F16(c, a, b)                                                         \
    asm volatile(                                                                \
        "mma.sync.aligned.m16n8k16.row.col.f32.f16.f16.f32 "                     \
        "{%0,%1,%2,%3},{%4,%5,%6,%7},{%8,%9},{%0,%1,%2,%3};"                     \
        : "+f"((c)[0]), "+f"((c)[1]), "+f"((c)[2]), "+f"((c)[3])                 \
        : "r"((a)[0]), "r"((a)[1]), "r"((a)[2]), "r"((a)[3]),                    \
          "r"((b)[0]), "r"((b)[1]))

__device__ __forceinline__ void ldmx4(uint32_t* r, uint32_t addr) {
    asm volatile("ldmatrix.sync.aligned.m8n8.x4.shared.b16 {%0,%1,%2,%3}, [%4];"
                 : "=r"(r[0]), "=r"(r[1]), "=r"(r[2]), "=r"(r[3]) : "r"(addr));
}
__device__ __forceinline__ void ldmx4t(uint32_t* r, uint32_t addr) {
    asm volatile("ldmatrix.sync.aligned.m8n8.x4.trans.shared.b16 {%0,%1,%2,%3}, [%4];"
                 : "=r"(r[0]), "=r"(r[1]), "=r"(r[2]), "=r"(r[3]) : "r"(addr));
}
__device__ __forceinline__ uint32_t h2u(half2 h) { return *reinterpret_cast<uint32_t*>(&h); }

// ---------------- fp32 -> fp16 conversion of X and the 4 weight matrices --------
#define XTOT4 (M_ * D_ / 4)     // 786432
#define WTOT4 (D_ * D_ / 4)     // 147456

__global__ __launch_bounds__(256)
void cvt_all(const float* __restrict__ X,
             const float* __restrict__ Wq, const float* __restrict__ Wk,
             const float* __restrict__ Wv, const float* __restrict__ Wo)
{
    int i = blockIdx.x * 256 + threadIdx.x;
    const int total = XTOT4 + 4 * WTOT4;
    if (i >= total) return;
    const float* src; half* dst; int off;
    if (i < XTOT4) { src = X; dst = g_Xh; off = i; }
    else {
        int j = i - XTOT4;
        int w = j / WTOT4;
        off = j - w * WTOT4;
        src = (w == 0) ? Wq : (w == 1) ? Wk : (w == 2) ? Wv : Wo;
        dst = (w == 0) ? g_Wqh : (w == 1) ? g_Wkh : (w == 2) ? g_Wvh : g_Woh;
    }
    float4 v = ((const float4*)src)[off];
    uint2 u = make_uint2(h2u(__floats2half2_rn(v.x, v.y)),
                         h2u(__floats2half2_rn(v.z, v.w)));
    ((uint2*)dst)[off] = u;
}

// ---------------- fp16 tensor-core GEMM mainloop (128x64 tile, k-chunk 64) ------
#define LDA 72

__device__ __forceinline__
void gemm_h_mainloop(const half* __restrict__ A, const half* __restrict__ W,
                     float c[2][4][4], half* As, half* Ws)
{
    const int tid  = threadIdx.x;
    const int lane = tid & 31;
    const int wid  = tid >> 5;
    const int wm   = wid & 3;
    const int wn   = wid >> 2;
    const int m0   = blockIdx.y * 128;
    const int n0   = blockIdx.x * 64;
    const int lrow = lane & 15;
    const int lcol = (lane >> 4) * 8;

#pragma unroll
    for (int mi = 0; mi < 2; mi++)
#pragma unroll
        for (int j = 0; j < 4; j++)
#pragma unroll
            for (int r = 0; r < 4; r++) c[mi][j][r] = 0.f;

    const uint32_t aaddr0 = (uint32_t)__cvta_generic_to_shared(
        &As[(wm * 32 + lrow) * LDA + lcol]);
    const uint32_t aaddr1 = aaddr0 + 16 * LDA * 2;
    const uint32_t baddr  = (uint32_t)__cvta_generic_to_shared(
        &Ws[lrow * LDA + wn * 32 + lcol]);

    for (int kk = 0; kk < D_; kk += 64) {
        // A tile 128x64 halves = 1024 uint4
#pragma unroll
        for (int r = 0; r < 4; r++) {
            int idx = tid + r * 256;
            int row = idx >> 3;
            int c8  = (idx & 7) * 8;
            *(uint4*)&As[row * LDA + c8] =
                *(const uint4*)(A + (size_t)(m0 + row) * D_ + kk + c8);
        }
        // W tile 64x64 halves = 512 uint4
#pragma unroll
        for (int r = 0; r < 2; r++) {
            int idx = tid + r * 256;
            int row = idx >> 3;
            int c8  = (idx & 7) * 8;
            *(uint4*)&Ws[row * LDA + c8] =
                *(const uint4*)(W + (size_t)(kk + row) * D_ + n0 + c8);
        }
        __syncthreads();

#pragma unroll
        for (int ks = 0; ks < 4; ks++) {
            uint32_t af[2][4];
            ldmx4(af[0], aaddr0 + ks * 32);
            ldmx4(af[1], aaddr1 + ks * 32);
#pragma unroll
            for (int ni = 0; ni < 2; ni++) {
                uint32_t bf[4];
                ldmx4t(bf, baddr + (ks * 16 * LDA + ni * 16) * 2);
                uint32_t b0[2] = { bf[0], bf[1] };
                uint32_t b1[2] = { bf[2], bf[3] };
                MMA_F16(c[0][ni * 2],     af[0], b0);
                MMA_F16(c[0][ni * 2 + 1], af[0], b1);
                MMA_F16(c[1][ni * 2],     af[1], b0);
                MMA_F16(c[1][ni * 2 + 1], af[1], b1);
            }
        }
        __syncthreads();
    }
}

// QKV projection: blockIdx.z selects matrix; epilogue scatters half into [B,H,T,Dh].
__global__ __launch_bounds__(256)
void gemm_qkv_h(const float* __restrict__ bq, const float* __restrict__ bk,
                const float* __restrict__ bv)
{
    __shared__ half As[128 * LDA];
    __shared__ half Ws[64 * LDA];

    const int z = blockIdx.z;
    const half*  W  = (z == 0) ? g_Wqh : (z == 1) ? g_Wkh : g_Wvh;
    const float* bb = (z == 0) ? bq    : (z == 1) ? bk    : bv;
    half*        Cd = (z == 0) ? g_Qh  : (z == 1) ? g_Kh  : g_Vh;

    float c[2][4][4];
    gemm_h_mainloop(g_Xh, W, c, As, Ws);

    const int lane = threadIdx.x & 31;
    const int wid  = threadIdx.x >> 5;
    const int wm   = wid & 3;
    const int wn   = wid >> 2;
    const int gr   = lane >> 2;
    const int gc   = lane & 3;
    const int m0   = blockIdx.y * 128;
    const int n0   = blockIdx.x * 64;

#pragma unroll
    for (int mi = 0; mi < 2; mi++) {
#pragma unroll
        for (int j = 0; j < 4; j++) {
            int col = n0 + wn * 32 + j * 8 + 2 * gc;
            float b0 = bb[col], b1 = bb[col + 1];
            int h  = col >> 6;
            int dh = col & 63;
#pragma unroll
            for (int hp = 0; hp < 2; hp++) {
                int row = m0 + wm * 32 + mi * 16 + gr + hp * 8;
                int bt  = row >> 11;        // / T_
                int t   = row & (T_ - 1);
                half2 v = __floats2half2_rn(c[mi][j][hp * 2] + b0,
                                            c[mi][j][hp * 2 + 1] + b1);
                *(half2*)&Cd[((size_t)(bt * H_ + h) * T_ + t) * DH_ + dh] = v;
            }
        }
    }
}

// Output projection: AO(half) @ Wo + bo -> fp32 out.
__global__ __launch_bounds__(256)
void gemm_out_h(const float* __restrict__ bo, float* __restrict__ out)
{
    __shared__ half As[128 * LDA];
    __shared__ half Ws[64 * LDA];

    float c[2][4][4];
    gemm_h_mainloop(g_AOh, g_Woh, c, As, Ws);

    const int lane = threadIdx.x & 31;
    const int wid  = threadIdx.x >> 5;
    const int wm   = wid & 3;
    const int wn   = wid >> 2;
    const int gr   = lane >> 2;
    const int gc   = lane & 3;
    const int m0   = blockIdx.y * 128;
    const int n0   = blockIdx.x * 64;

#pragma unroll
    for (int mi = 0; mi < 2; mi++) {
#pragma unroll
        for (int j = 0; j < 4; j++) {
            int col = n0 + wn * 32 + j * 8 + 2 * gc;
            float b0 = bo[col], b1 = bo[col + 1];
#pragma unroll
            for (int hp = 0; hp < 2; hp++) {
                int row = m0 + wm * 32 + mi * 16 + gr + hp * 8;
                *(float2*)&out[(size_t)row * D_ + col] =
                    make_float2(c[mi][j][hp * 2] + b0, c[mi][j][hp * 2 + 1] + b1);
            }
        }
    }
}

// ---------------- V suffix sums per (b,h): VS[t] = sum_{j>t} V[j] ----------------
__global__ __launch_bounds__(64)
void vsuffix_a()
{
    const int bh = blockIdx.y;
    const int ch = blockIdx.x;                 // 0..63, 32 rows each
    const int d  = threadIdx.x;
    const half* V = g_Vh + (size_t)bh * T_ * DH_;
    float*      S = g_VS + (size_t)bh * T_ * DH_;
    const int t0 = ch * 32;
    float sum = 0.f;
#pragma unroll 8
    for (int t = t0 + 31; t >= t0; t--) {
        S[(size_t)t * DH_ + d] = sum;
        sum += __half2float(V[(size_t)t * DH_ + d]);
    }
    g_CT[((size_t)bh * 64 + ch) * DH_ + d] = sum;
}

__global__ __launch_bounds__(64)
void vsuffix_b()
{
    const int bh = blockIdx.y;
    const int ch = blockIdx.x;
    const int d  = threadIdx.x;
    if (ch == 63) return;
    float off = 0.f;
#pragma unroll 8
    for (int cc = ch + 1; cc < 64; cc++)
        off += g_CT[((size_t)bh * 64 + cc) * DH_ + d];
    float* S = g_VS + (size_t)bh * T_ * DH_;
    const int t0 = ch * 32;
#pragma unroll 8
    for (int t = t0; t < t0 + 32; t++)
        S[(size_t)t * DH_ + d] += off;
}

// ---------------- fp16 tensor-core causal attention (FA2 style) -----------------
// 8 warps = 4 (m16 q-row groups) x 2 (32-key halves). P never touches smem.
#define LDH 72

__global__ __launch_bounds__(256, 2)
void attn_tc()
{
    __shared__ __align__(16) uint8_t smraw[3 * 64 * LDH * 2 + 4 * 16 * 64 * 4 + 64 * 4];
    half* Qh = (half*)smraw;
    half* Kh = Qh + 64 * LDH;
    half* Vh = Kh + 64 * LDH;
    float* redO = (float*)(smraw + 3 * 64 * LDH * 2);
    float* redS = redO + 4 * 16 * 64;

    const int tid  = threadIdx.x;
    const int lane = tid & 31;
    const int wid  = tid >> 5;
    const int wm   = wid & 3;
    const int wh   = wid >> 2;
    const int gr   = lane >> 2;
    const int gc   = lane & 3;
    const int lrow = lane & 15;
    const int lcol = (lane >> 4) * 8;

    const int bh = blockIdx.y;
    const int qt = gridDim.x - 1 - blockIdx.x;    // heavy tiles first
    const int q0 = qt * 64;

    const half*  Qg   = g_Qh + (size_t)bh * T_ * DH_;
    const half*  Kg   = g_Kh + (size_t)bh * T_ * DH_;
    const half*  Vg   = g_Vh + (size_t)bh * T_ * DH_;
    const float* Vsuf = g_VS + (size_t)bh * T_ * DH_;

    // ---- load Q tile (raw half copy), hoist Q fragments ----
#pragma unroll
    for (int rr = 0; rr < 2; rr++) {
        int i2  = tid + rr * 256;                 // 0..511
        int row = i2 >> 3;
        int c8  = (i2 & 7) * 8;
        *(uint4*)&Qh[row * LDH + c8] =
            *(const uint4*)(Qg + (size_t)(q0 + row) * DH_ + c8);
    }
    __syncthreads();

    uint32_t qf[4][4];
    {
        uint32_t qaddr = (uint32_t)__cvta_generic_to_shared(
            &Qh[(wm * 16 + lrow) * LDH + lcol]);
#pragma unroll
        for (int ks = 0; ks < 4; ks++)
            ldmx4(qf[ks], qaddr + ks * 32);
    }

    float o[8][4];
#pragma unroll
    for (int ni = 0; ni < 8; ni++)
#pragma unroll
        for (int r = 0; r < 4; r++) o[ni][r] = 0.f;
    float rsum0 = 0.f, rsum1 = 0.f;

    const uint32_t kaddr0 = (uint32_t)__cvta_generic_to_shared(
        &Kh[(wh * 32 + lrow) * LDH + lcol]);
    const uint32_t kaddr1 = kaddr0 + 16 * LDH * 2;
    const uint32_t vaddr0 = (uint32_t)__cvta_generic_to_shared(
        &Vh[(wh * 32 + lrow) * LDH + lcol]);
    const uint32_t vaddr1 = vaddr0 + 16 * LDH * 2;

    for (int kt = 0; kt <= qt; kt++) {
        __syncthreads();
        // ---- raw half K,V tile copy: 2+2 uint4 per thread ----
#pragma unroll
        for (int rr = 0; rr < 2; rr++) {
            int i2  = tid + rr * 256;
            int row = i2 >> 3;
            int c8  = (i2 & 7) * 8;
            const size_t goff = (size_t)(kt * 64 + row) * DH_ + c8;
            *(uint4*)&Kh[row * LDH + c8] = *(const uint4*)(Kg + goff);
            *(uint4*)&Vh[row * LDH + c8] = *(const uint4*)(Vg + goff);
        }
        __syncthreads();

        // ---- S = Q . K^T over this warp's 32 keys ----
        float s[4][4];
#pragma unroll
        for (int j = 0; j < 4; j++)
#pragma unroll
            for (int r = 0; r < 4; r++) s[j][r] = 0.f;

#pragma unroll
        for (int ks = 0; ks < 4; ks++) {
            uint32_t r0[4], r1[4];
            ldmx4(r0, kaddr0 + ks * 32);
            ldmx4(r1, kaddr1 + ks * 32);
            uint32_t b0[2] = { r0[0], r0[2] };
            uint32_t b1[2] = { r0[1], r0[3] };
            uint32_t b2[2] = { r1[0], r1[2] };
            uint32_t b3[2] = { r1[1], r1[3] };
            MMA_F16(s[0], qf[ks], b0);
            MMA_F16(s[1], qf[ks], b1);
            MMA_F16(s[2], qf[ks], b2);
            MMA_F16(s[3], qf[ks], b3);
        }

        // ---- exp + diag mask + rowsum; pack P as fp16 A-fragments ----
        const bool diag = (kt == qt);
        const int row0 = q0 + wm * 16 + gr;
        uint32_t pl[4], ph[4];
#pragma unroll
        for (int j = 0; j < 4; j++) {
            int colg = kt * 64 + wh * 32 + j * 8 + 2 * gc;
            float p0 = (diag && colg     > row0)     ? 0.f : __expf(s[j][0] * 0.125f);
            float p1 = (diag && colg + 1 > row0)     ? 0.f : __expf(s[j][1] * 0.125f);
            float p2 = (diag && colg     > row0 + 8) ? 0.f : __expf(s[j][2] * 0.125f);
            float p3 = (diag && colg + 1 > row0 + 8) ? 0.f : __expf(s[j][3] * 0.125f);
            rsum0 += p0 + p1;
            rsum1 += p2 + p3;
            pl[j] = h2u(__floats2half2_rn(p0, p1));
            ph[j] = h2u(__floats2half2_rn(p2, p3));
        }

        // ---- O += P . V ----
#pragma unroll
        for (int ks2 = 0; ks2 < 2; ks2++) {
            uint32_t a[4] = { pl[ks2 * 2], ph[ks2 * 2], pl[ks2 * 2 + 1], ph[ks2 * 2 + 1] };
            uint32_t vbase = (ks2 == 0) ? vaddr0 : vaddr1;
#pragma unroll
            for (int dg = 0; dg < 4; dg++) {
                uint32_t rv[4];
                ldmx4t(rv, vbase + dg * 32);
                uint32_t bA[2] = { rv[0], rv[1] };
                uint32_t bB[2] = { rv[2], rv[3] };
                MMA_F16(o[dg * 2],     a, bA);
                MMA_F16(o[dg * 2 + 1], a, bB);
            }
        }
    }

    // ---- rowsum reduce over gc lanes ----
    rsum0 += __shfl_xor_sync(0xffffffffu, rsum0, 1);
    rsum0 += __shfl_xor_sync(0xffffffffu, rsum0, 2);
    rsum1 += __shfl_xor_sync(0xffffffffu, rsum1, 1);
    rsum1 += __shfl_xor_sync(0xffffffffu, rsum1, 2);

    __syncthreads();
    if (wh == 0) {
        if (gc == 0) {
            redS[wm * 16 + gr]     = rsum0;
            redS[wm * 16 + 8 + gr] = rsum1;
        }
#pragma unroll
        for (int ni = 0; ni < 8; ni++) {
            int c = ni * 8 + 2 * gc;
            *(float2*)&redO[(wm * 16 + gr) * 64 + c]     = make_float2(o[ni][0], o[ni][1]);
            *(float2*)&redO[(wm * 16 + 8 + gr) * 64 + c] = make_float2(o[ni][2], o[ni][3]);
        }
    }
    __syncthreads();

    if (wh == 1) {
        const int b = bh / H_;
        const int h = bh - b * H_;
#pragma unroll
        for (int half_ = 0; half_ < 2; half_++) {
            int rl = wm * 16 + gr + 8 * half_;
            int qi = q0 + rl;
            float own = (half_ == 0) ? rsum0 : rsum1;
            float denom = own + redS[rl] + (float)(T_ - 1 - qi);
            float inv = 1.f / denom;
            half* dst = g_AOh + ((size_t)(b * T_ + qi)) * D_ + h * DH_;
            const float* vs = Vsuf + (size_t)qi * DH_;
#pragma unroll
            for (int ni = 0; ni < 8; ni++) {
                int c = ni * 8 + 2 * gc;
                float2 red = *(const float2*)&redO[rl * 64 + c];
                float2 vsv = *(const float2*)&vs[c];
                float v0 = (o[ni][half_ * 2 + 0] + red.x + vsv.x) * inv;
                float v1 = (o[ni][half_ * 2 + 1] + red.y + vsv.y) * inv;
                *(half2*)&dst[c] = __floats2half2_rn(v0, v1);
            }
        }
    }
}

// ---------------- launch -----------------
extern "C" void kernel_launch(void* const* d_in, const int* in_sizes, int n_in,
                              void* d_out, int out_size)
{
    const float* X  = (const float*)d_in[0];
    const float* Wq = (const float*)d_in[1];
    const float* bq = (const float*)d_in[2];
    const float* Wk = (const float*)d_in[3];
    const float* bk = (const float*)d_in[4];
    const float* Wv = (const float*)d_in[5];
    const float* bv = (const float*)d_in[6];
    const float* Wo = (const float*)d_in[7];
    const float* bo = (const float*)d_in[8];
    float* out = (float*)d_out;

    const int total4 = XTOT4 + 4 * WTOT4;
    cvt_all<<<(total4 + 255) / 256, 256>>>(X, Wq, Wk, Wv, Wo);
    gemm_qkv_h<<<dim3(D_ / 64, M_ / 128, 3), 256>>>(bq, bk, bv);
    vsuffix_a<<<dim3(64, 24), 64>>>();
    vsuffix_b<<<dim3(64, 24), 64>>>();
    attn_tc<<<dim3(T_ / 64, B_ * H_), 256>>>();
    gemm_out_h<<<dim3(D_ / 64, M_ / 128), 256>>>(bo, out);
}